// round 14
// baseline (speedup 1.0000x reference)
#include <cuda_runtime.h>

// PillarFeatureNet fused kernel, sm_103a.
// Algebra: BN folded into weights; 9-feature input collapsed to affine form in
// (x,y,z,r) with per-pillar effective bias; masked points skipped; layer-2 GEMV
// done with packed fp32x2 FMA (2 points per instruction), W2 column resident in
// registers of a persistent block. Layer-1 results for ALL point pairs are
// staged in shared behind a single barrier so the layer-2 loop is barrier-free.
//
// NOTE: pillar_coords / num_points_per_pillar are int32 on the device (JAX
// canonicalizes the requested int64 to int32 without x64 mode).

#define RES_ 0.16f
#define XMIN_ -51.2f
#define YMIN_ -51.2f
#define EPS_ 1e-5f
#define NEG_ -1000000000.0f

typedef unsigned long long ull;

// Folded parameters (computed once per launch by prep_kernel)
__device__ float g_A[7 * 64];     // rows: A0(x) A1(y) A2(z) A3(r) Bxc Byc Bzm
__device__ float g_b1f[64];
__device__ float g_b2f[64];
__device__ float g_W2f[64 * 64];  // [k][c], BN2-scaled

__device__ __forceinline__ ull pack2(float lo, float hi) {
    ull r;
    asm("mov.b64 %0, {%1, %2};" : "=l"(r) : "f"(lo), "f"(hi));
    return r;
}
__device__ __forceinline__ void unpack2(ull v, float& lo, float& hi) {
    asm("mov.b64 {%0, %1}, %2;" : "=f"(lo), "=f"(hi) : "l"(v));
}
__device__ __forceinline__ void ffma2(ull& d, ull a, ull b) {
    asm("fma.rn.f32x2 %0, %1, %2, %0;" : "+l"(d) : "l"(a), "l"(b));
}

__global__ void prep_kernel(
    const float* __restrict__ W1, const float* __restrict__ b1,
    const float* __restrict__ g1, const float* __restrict__ beta1,
    const float* __restrict__ m1, const float* __restrict__ v1,
    const float* __restrict__ W2, const float* __restrict__ b2,
    const float* __restrict__ g2, const float* __restrict__ beta2,
    const float* __restrict__ m2, const float* __restrict__ v2)
{
    int c = threadIdx.x;  // 0..63 = channel
    float s1 = g1[c] * rsqrtf(v1[c] + EPS_);
    float w0 = W1[0 * 64 + c], w1 = W1[1 * 64 + c], w2 = W1[2 * 64 + c];
    float w3 = W1[3 * 64 + c], w4 = W1[4 * 64 + c], w5 = W1[5 * 64 + c];
    float w6 = W1[6 * 64 + c], w7 = W1[7 * 64 + c], w8 = W1[8 * 64 + c];
    // feat = [x,y,z,r,xo,yo,zo,xo,yo]; xo=x-xc, yo=y-yc, zo=z-zmean
    float bxc = (w4 + w7) * s1;
    float byc = (w5 + w8) * s1;
    float bzm = w6 * s1;
    g_A[0 * 64 + c] = (w0 + w4 + w7) * s1;  // coeff of x
    g_A[1 * 64 + c] = (w1 + w5 + w8) * s1;  // coeff of y
    g_A[2 * 64 + c] = (w2 + w6) * s1;       // coeff of z
    g_A[3 * 64 + c] = w3 * s1;              // coeff of r
    g_A[4 * 64 + c] = bxc;
    g_A[5 * 64 + c] = byc;
    g_A[6 * 64 + c] = bzm;
    g_b1f[c] = b1[c] * s1 + beta1[c] - m1[c] * s1;

    float s2 = g2[c] * rsqrtf(v2[c] + EPS_);
    g_b2f[c] = b2[c] * s2 + beta2[c] - m2[c] * s2;
    for (int k = 0; k < 64; k++)
        g_W2f[k * 64 + c] = W2[k * 64 + c] * s2;
}

__global__ __launch_bounds__(64) void pfn_kernel(
    const float* __restrict__ pillars,   // [P][32][4] f32
    const int* __restrict__ coords,      // [P][2] i32 (row, col)
    const int* __restrict__ npp,         // [P] i32
    float* __restrict__ out,             // [P][64] f32
    int P)
{
    __shared__ __align__(16) float4 sh_pts[32];      // (x,y,z,r) per point
    __shared__ __align__(16) float2 sh_h1[16][64];   // h1 pairs for ALL pairs (8 KB)
    __shared__ float sh_zm;

    const int t = threadIdx.x;  // output channel

    // Persistent per-channel constants (loaded once per block)
    const float a0 = g_A[0 * 64 + t], a1 = g_A[1 * 64 + t];
    const float a2 = g_A[2 * 64 + t], a3 = g_A[3 * 64 + t];
    const float bxc = g_A[4 * 64 + t], byc = g_A[5 * 64 + t], bzm = g_A[6 * 64 + t];
    const float bb1 = g_b1f[t];
    const float b2v = g_b2f[t];
    const ull b2p = pack2(b2v, b2v);

    // W2 column for this channel, duplicated into f32x2 packs (128 regs)
    ull w2p[64];
#pragma unroll
    for (int k = 0; k < 64; k++) {
        float w = g_W2f[k * 64 + t];
        w2p[k] = pack2(w, w);
    }

    for (int p = blockIdx.x; p < P; p += gridDim.x) {
        const int np = npp[p];
        const float xc = ((float)coords[2 * p + 1] + 0.5f) * RES_ + XMIN_;
        const float yc = ((float)coords[2 * p + 0] + 0.5f) * RES_ + YMIN_;

        // Cooperative load of all 32 points (512B coalesced)
        ((float2*)sh_pts)[t] = ((const float2*)pillars)[(size_t)p * 64 + t];
        __syncthreads();

        // z-mean over valid points (warp 0 butterfly)
        if (t < 32) {
            float z = (t < np) ? sh_pts[t].z : 0.f;
#pragma unroll
            for (int o = 16; o > 0; o >>= 1)
                z += __shfl_xor_sync(0xffffffffu, z, o);
            if (t == 0) sh_zm = z / fmaxf((float)np, 1.f);
        }
        __syncthreads();

        const float b1e = bb1 - xc * bxc - yc * byc - sh_zm * bzm;
        const int npairs = (np + 1) >> 1;

        // Layer 1 (+relu) for ALL pairs of this pillar, staged behind ONE barrier
        for (int j = 0; j < npairs; j++) {
            const int m0 = 2 * j;
            const int m1 = (2 * j + 1 < np) ? 2 * j + 1 : 2 * j;  // dup last if odd
            const float4 q0 = sh_pts[m0];
            const float4 q1 = sh_pts[m1];
            float h0 = fmaf(q0.w, a3, fmaf(q0.z, a2, fmaf(q0.y, a1, fmaf(q0.x, a0, b1e))));
            float h1 = fmaf(q1.w, a3, fmaf(q1.z, a2, fmaf(q1.y, a1, fmaf(q1.x, a0, b1e))));
            sh_h1[j][t] = make_float2(fmaxf(h0, 0.f), fmaxf(h1, 0.f));
        }
        __syncthreads();

        // Layer 2: barrier-free loop over pairs; 64-wide dot for 2 points at
        // once via fp32x2 packed FMA against the register-resident W2 column.
        float runmax = NEG_;
        for (int j = 0; j < npairs; j++) {
            ull acc0 = b2p;   // carries bias in both halves
            ull acc1 = 0ull;  // {0.f, 0.f}
            const ulonglong2* hb = (const ulonglong2*)sh_h1[j];
#pragma unroll
            for (int i = 0; i < 32; i++) {
                ulonglong2 hv = hb[i];  // channels k=2i, 2i+1 (broadcast)
                ffma2(acc0, hv.x, w2p[2 * i]);
                ffma2(acc1, hv.y, w2p[2 * i + 1]);
            }
            float l0, u0, l1, u1;
            unpack2(acc0, l0, u0);
            unpack2(acc1, l1, u1);
            // relu deferred to the end (max over relu == relu(max), all >= 0)
            runmax = fmaxf(runmax, fmaxf(l0 + l1, u0 + u1));
        }
        __syncthreads();  // protect sh_h1/sh_pts before next pillar overwrites

        out[(size_t)p * 64 + t] = (np > 0) ? fmaxf(runmax, 0.f) : NEG_;
    }
}

extern "C" void kernel_launch(void* const* d_in, const int* in_sizes, int n_in,
                              void* d_out, int out_size) {
    const float* pillars = (const float*)d_in[0];
    const int* coords    = (const int*)d_in[1];
    const int* npp       = (const int*)d_in[2];
    const float* W1    = (const float*)d_in[3];
    const float* b1    = (const float*)d_in[4];
    const float* g1    = (const float*)d_in[5];
    const float* beta1 = (const float*)d_in[6];
    const float* m1    = (const float*)d_in[7];
    const float* v1    = (const float*)d_in[8];
    const float* W2    = (const float*)d_in[9];
    const float* b2    = (const float*)d_in[10];
    const float* g2    = (const float*)d_in[11];
    const float* beta2 = (const float*)d_in[12];
    const float* m2    = (const float*)d_in[13];
    const float* v2    = (const float*)d_in[14];
    float* out = (float*)d_out;

    const int P = in_sizes[0] / (32 * 4);

    prep_kernel<<<1, 64>>>(W1, b1, g1, beta1, m1, v1, W2, b2, g2, beta2, m2, v2);
    pfn_kernel<<<592, 64>>>(pillars, coords, npp, out, P);
}

// round 15
// speedup vs baseline: 1.4979x; 1.4979x over previous
#include <cuda_runtime.h>

// PillarFeatureNet fused kernel, sm_103a — R15.
// vs R14 (819us): (1) W2 column split across 2 k-halves so the per-thread pack
// array is 32 ull = 64 regs -> actually register-resident (R14's 64-ull array
// spilled to local: regs=96 < 128 needed, L1=47%). (2) 128-thread blocks so all
// 4 SMSPs get warps (64-thread blocks only populate SMSP 0/1 via wid%4).
// Halves combine through a shared partial buffer, +1 barrier per pillar.
//
// Algebra unchanged: BN folded; 9 input features collapsed to affine in
// (x,y,z,r) + per-pillar bias; only valid points computed; packed fp32x2 FMA
// does 2 points per instruction; relu deferred past the max.
//
// coords / num_points are int32 (JAX canonicalizes int64 -> int32).

#define RES_ 0.16f
#define XMIN_ -51.2f
#define YMIN_ -51.2f
#define EPS_ 1e-5f
#define NEG_ -1000000000.0f

typedef unsigned long long ull;

__device__ float g_A[7 * 64];     // rows: A0(x) A1(y) A2(z) A3(r) Bxc Byc Bzm
__device__ float g_b1f[64];
__device__ float g_b2f[64];
__device__ float g_W2f[64 * 64];  // [k][c], BN2-scaled

__device__ __forceinline__ ull pack2(float lo, float hi) {
    ull r;
    asm("mov.b64 %0, {%1, %2};" : "=l"(r) : "f"(lo), "f"(hi));
    return r;
}
__device__ __forceinline__ void unpack2(ull v, float& lo, float& hi) {
    asm("mov.b64 {%0, %1}, %2;" : "=f"(lo), "=f"(hi) : "l"(v));
}
__device__ __forceinline__ void ffma2(ull& d, ull a, ull b) {
    asm("fma.rn.f32x2 %0, %1, %2, %0;" : "+l"(d) : "l"(a), "l"(b));
}

__global__ void prep_kernel(
    const float* __restrict__ W1, const float* __restrict__ b1,
    const float* __restrict__ g1, const float* __restrict__ beta1,
    const float* __restrict__ m1, const float* __restrict__ v1,
    const float* __restrict__ W2, const float* __restrict__ b2,
    const float* __restrict__ g2, const float* __restrict__ beta2,
    const float* __restrict__ m2, const float* __restrict__ v2)
{
    int c = threadIdx.x;  // 0..63 = channel
    float s1 = g1[c] * rsqrtf(v1[c] + EPS_);
    float w0 = W1[0 * 64 + c], w1 = W1[1 * 64 + c], w2 = W1[2 * 64 + c];
    float w3 = W1[3 * 64 + c], w4 = W1[4 * 64 + c], w5 = W1[5 * 64 + c];
    float w6 = W1[6 * 64 + c], w7 = W1[7 * 64 + c], w8 = W1[8 * 64 + c];
    // feat = [x,y,z,r,xo,yo,zo,xo,yo]; xo=x-xc, yo=y-yc, zo=z-zmean
    g_A[0 * 64 + c] = (w0 + w4 + w7) * s1;  // coeff of x
    g_A[1 * 64 + c] = (w1 + w5 + w8) * s1;  // coeff of y
    g_A[2 * 64 + c] = (w2 + w6) * s1;       // coeff of z
    g_A[3 * 64 + c] = w3 * s1;              // coeff of r
    g_A[4 * 64 + c] = (w4 + w7) * s1;       // * xc
    g_A[5 * 64 + c] = (w5 + w8) * s1;       // * yc
    g_A[6 * 64 + c] = w6 * s1;              // * zmean
    g_b1f[c] = b1[c] * s1 + beta1[c] - m1[c] * s1;

    float s2 = g2[c] * rsqrtf(v2[c] + EPS_);
    g_b2f[c] = b2[c] * s2 + beta2[c] - m2[c] * s2;
    for (int k = 0; k < 64; k++)
        g_W2f[k * 64 + c] = W2[k * 64 + c] * s2;
}

__global__ __launch_bounds__(128, 4) void pfn_kernel(
    const float* __restrict__ pillars,   // [P][32][4] f32
    const int* __restrict__ coords,      // [P][2] i32 (row, col)
    const int* __restrict__ npp,         // [P] i32
    float* __restrict__ out,             // [P][64] f32
    int P)
{
    __shared__ __align__(16) float4 sh_pts[32];         // (x,y,z,r) per point
    __shared__ __align__(16) float2 sh_h1[16][64];      // h1 pairs, all pairs (8KB)
    __shared__ __align__(16) float2 sh_part[2][16][64]; // per-half partial dots (16KB)
    __shared__ float sh_zm;

    const int t = threadIdx.x;
    const int c = t & 63;        // output channel
    const int half = t >> 6;     // k-half: 0 -> k in [0,32), 1 -> k in [32,64)

    // Per-channel layer-1 constants
    const float a0 = g_A[0 * 64 + c], a1 = g_A[1 * 64 + c];
    const float a2 = g_A[2 * 64 + c], a3 = g_A[3 * 64 + c];
    const float bxc = g_A[4 * 64 + c], byc = g_A[5 * 64 + c], bzm = g_A[6 * 64 + c];
    const float bb1 = g_b1f[c];
    const float b2v = g_b2f[c];

    // This thread's 32 W2 packs (64 registers — fits, no spill)
    ull w2p[32];
#pragma unroll
    for (int i = 0; i < 32; i++) {
        float w = g_W2f[(half * 32 + i) * 64 + c];
        w2p[i] = pack2(w, w);
    }

    for (int p = blockIdx.x; p < P; p += gridDim.x) {
        const int np = npp[p];
        const float xc = ((float)coords[2 * p + 1] + 0.5f) * RES_ + XMIN_;
        const float yc = ((float)coords[2 * p + 0] + 0.5f) * RES_ + YMIN_;

        // Cooperative load of all 32 points (512B coalesced, 1 float/thread)
        ((float*)sh_pts)[t] = pillars[(size_t)p * 128 + t];
        __syncthreads();

        // z-mean over valid points (warp 0 butterfly)
        if (t < 32) {
            float z = (t < np) ? sh_pts[t].z : 0.f;
#pragma unroll
            for (int o = 16; o > 0; o >>= 1)
                z += __shfl_xor_sync(0xffffffffu, z, o);
            if (t == 0) sh_zm = z / fmaxf((float)np, 1.f);
        }
        __syncthreads();

        const float b1e = bb1 - xc * bxc - yc * byc - sh_zm * bzm;
        const int npairs = (np + 1) >> 1;

        // Layer 1 (+relu): halves split the pairs (interleaved), one barrier
        for (int j = half; j < npairs; j += 2) {
            const int m0 = 2 * j;
            const int m1 = (2 * j + 1 < np) ? 2 * j + 1 : 2 * j;  // dup last if odd
            const float4 q0 = sh_pts[m0];
            const float4 q1 = sh_pts[m1];
            float h0 = fmaf(q0.w, a3, fmaf(q0.z, a2, fmaf(q0.y, a1, fmaf(q0.x, a0, b1e))));
            float h1 = fmaf(q1.w, a3, fmaf(q1.z, a2, fmaf(q1.y, a1, fmaf(q1.x, a0, b1e))));
            sh_h1[j][c] = make_float2(fmaxf(h0, 0.f), fmaxf(h1, 0.f));
        }
        __syncthreads();

        // Layer 2: each thread does a 32-deep half-dot for 2 points at once
        // (fp32x2) against its register-resident W2 packs. Barrier-free loop.
        for (int j = 0; j < npairs; j++) {
            ull acc0 = 0ull, acc1 = 0ull;  // two chains: even/odd k
            const ulonglong2* hb = (const ulonglong2*)sh_h1[j] + half * 16;
#pragma unroll
            for (int i = 0; i < 16; i++) {
                ulonglong2 hv = hb[i];  // channels k = half*32 + 2i, +2i+1 (broadcast)
                ffma2(acc0, hv.x, w2p[2 * i]);
                ffma2(acc1, hv.y, w2p[2 * i + 1]);
            }
            float l0, u0, l1, u1;
            unpack2(acc0, l0, u0);
            unpack2(acc1, l1, u1);
            sh_part[half][j][c] = make_float2(l0 + l1, u0 + u1);
        }
        __syncthreads();

        // Combine halves + bias, running max; relu after max (valid h >= 0)
        float runmax = NEG_;
        for (int j = 0; j < npairs; j++) {
            const float2 pa = sh_part[0][j][c];
            const float2 pb = sh_part[1][j][c];
            const float sl = pa.x + pb.x + b2v;
            const float su = pa.y + pb.y + b2v;
            runmax = fmaxf(runmax, fmaxf(sl, su));
        }
        if (t < 64)
            out[(size_t)p * 64 + c] = (np > 0) ? fmaxf(runmax, 0.f) : NEG_;
        // no trailing barrier needed: next pillar has 3 barriers before any
        // thread rewrites sh_part, and sh_pts/sh_h1 aren't read past their syncs
    }
}

extern "C" void kernel_launch(void* const* d_in, const int* in_sizes, int n_in,
                              void* d_out, int out_size) {
    const float* pillars = (const float*)d_in[0];
    const int* coords    = (const int*)d_in[1];
    const int* npp       = (const int*)d_in[2];
    const float* W1    = (const float*)d_in[3];
    const float* b1    = (const float*)d_in[4];
    const float* g1    = (const float*)d_in[5];
    const float* beta1 = (const float*)d_in[6];
    const float* m1    = (const float*)d_in[7];
    const float* v1    = (const float*)d_in[8];
    const float* W2    = (const float*)d_in[9];
    const float* b2    = (const float*)d_in[10];
    const float* g2    = (const float*)d_in[11];
    const float* beta2 = (const float*)d_in[12];
    const float* m2    = (const float*)d_in[13];
    const float* v2    = (const float*)d_in[14];
    float* out = (float*)d_out;

    const int P = in_sizes[0] / (32 * 4);

    prep_kernel<<<1, 64>>>(W1, b1, g1, beta1, m1, v1, W2, b2, g2, beta2, m2, v2);
    pfn_kernel<<<592, 128>>>(pillars, coords, npp, out, P);
}

// round 16
// speedup vs baseline: 1.8517x; 1.2362x over previous
#include <cuda_runtime.h>

// PillarFeatureNet fused kernel, sm_103a — R16.
// vs R15 (547us, L1=80%/fma=36%): layer-2 remapped so each thread covers TWO
// channels (c2, c2+32) over a 16-deep k-quarter (warp == k-group). Per pair per
// warp: 8 broadcast LDS.128 feed 32 FFMA2 (was 16:32) -> shared-pipe pressure
// halved while fp32x2 FMA work is unchanged (it sits at its issue floor).
// Partials combine via a bank-conflict-free [j][kg][c] layout, with the
// combine pass split across pair-parity instead of running redundantly on all
// threads. 4 accumulator chains cover fma lat4/rt2.
//
// Algebra unchanged: BN folded; 9 input features collapsed to affine in
// (x,y,z,r) + per-pillar bias; only valid points computed; fp32x2 packs the
// two points of a pair; relu deferred past the max; bias added after the max.
//
// coords / num_points are int32 (JAX canonicalizes int64 -> int32).

#define RES_ 0.16f
#define XMIN_ -51.2f
#define YMIN_ -51.2f
#define EPS_ 1e-5f
#define NEG_ -1000000000.0f

typedef unsigned long long ull;

__device__ float g_A[7 * 64];     // rows: A0(x) A1(y) A2(z) A3(r) Bxc Byc Bzm
__device__ float g_b1f[64];
__device__ float g_b2f[64];
__device__ float g_W2f[64 * 64];  // [k][c], BN2-scaled

__device__ __forceinline__ ull pack2(float lo, float hi) {
    ull r;
    asm("mov.b64 %0, {%1, %2};" : "=l"(r) : "f"(lo), "f"(hi));
    return r;
}
__device__ __forceinline__ void unpack2(ull v, float& lo, float& hi) {
    asm("mov.b64 {%0, %1}, %2;" : "=f"(lo), "=f"(hi) : "l"(v));
}
__device__ __forceinline__ void ffma2(ull& d, ull a, ull b) {
    asm("fma.rn.f32x2 %0, %1, %2, %0;" : "+l"(d) : "l"(a), "l"(b));
}
__device__ __forceinline__ void fadd2(ull& d, ull a, ull b) {
    asm("add.rn.f32x2 %0, %1, %2;" : "=l"(d) : "l"(a), "l"(b));
}

__global__ void prep_kernel(
    const float* __restrict__ W1, const float* __restrict__ b1,
    const float* __restrict__ g1, const float* __restrict__ beta1,
    const float* __restrict__ m1, const float* __restrict__ v1,
    const float* __restrict__ W2, const float* __restrict__ b2,
    const float* __restrict__ g2, const float* __restrict__ beta2,
    const float* __restrict__ m2, const float* __restrict__ v2)
{
    int c = threadIdx.x;  // 0..63 = channel
    float s1 = g1[c] * rsqrtf(v1[c] + EPS_);
    float w0 = W1[0 * 64 + c], w1 = W1[1 * 64 + c], w2 = W1[2 * 64 + c];
    float w3 = W1[3 * 64 + c], w4 = W1[4 * 64 + c], w5 = W1[5 * 64 + c];
    float w6 = W1[6 * 64 + c], w7 = W1[7 * 64 + c], w8 = W1[8 * 64 + c];
    // feat = [x,y,z,r,xo,yo,zo,xo,yo]; xo=x-xc, yo=y-yc, zo=z-zmean
    g_A[0 * 64 + c] = (w0 + w4 + w7) * s1;  // coeff of x
    g_A[1 * 64 + c] = (w1 + w5 + w8) * s1;  // coeff of y
    g_A[2 * 64 + c] = (w2 + w6) * s1;       // coeff of z
    g_A[3 * 64 + c] = w3 * s1;              // coeff of r
    g_A[4 * 64 + c] = (w4 + w7) * s1;       // * xc
    g_A[5 * 64 + c] = (w5 + w8) * s1;       // * yc
    g_A[6 * 64 + c] = w6 * s1;              // * zmean
    g_b1f[c] = b1[c] * s1 + beta1[c] - m1[c] * s1;

    float s2 = g2[c] * rsqrtf(v2[c] + EPS_);
    g_b2f[c] = b2[c] * s2 + beta2[c] - m2[c] * s2;
    for (int k = 0; k < 64; k++)
        g_W2f[k * 64 + c] = W2[k * 64 + c] * s2;
}

__global__ __launch_bounds__(128, 4) void pfn_kernel(
    const float* __restrict__ pillars,   // [P][32][4] f32
    const int* __restrict__ coords,      // [P][2] i32 (row, col)
    const int* __restrict__ npp,         // [P] i32
    float* __restrict__ out,             // [P][64] f32
    int P)
{
    __shared__ __align__(16) float4 sh_pts[32];     // (x,y,z,r) per point
    __shared__ __align__(16) float2 sh_h1[16][64];  // h1 pairs, all pairs (8KB)
    __shared__ __align__(16) ull sh_part[16][4][64];// [pair][kgroup][chan] (32KB)
    __shared__ float sh_max[2][64];                 // per-pair-parity run max
    __shared__ float sh_zm;

    const int t = threadIdx.x;
    const int c64 = t & 63;      // channel for layer-1 / combine / output
    const int half = t >> 6;     // splits layer-1 pairs; pair-parity in combine
    const int c2 = t & 31;       // layer-2 channel base (owns c2 and c2+32)
    const int kg = t >> 5;       // layer-2 k-group == warp id (k in [16kg,16kg+16))

    // Per-channel layer-1 constants
    const float a0 = g_A[0 * 64 + c64], a1 = g_A[1 * 64 + c64];
    const float a2 = g_A[2 * 64 + c64], a3 = g_A[3 * 64 + c64];
    const float bxc = g_A[4 * 64 + c64], byc = g_A[5 * 64 + c64], bzm = g_A[6 * 64 + c64];
    const float bb1 = g_b1f[c64];
    const float b2v = g_b2f[c64];

    // W2 packs: w2p[0..15] = channel c2, k = 16kg+i ; w2p[16..31] = channel c2+32
    ull w2p[32];
#pragma unroll
    for (int i = 0; i < 16; i++) {
        float wa = g_W2f[(kg * 16 + i) * 64 + c2];
        float wb = g_W2f[(kg * 16 + i) * 64 + c2 + 32];
        w2p[i]      = pack2(wa, wa);
        w2p[16 + i] = pack2(wb, wb);
    }

    for (int p = blockIdx.x; p < P; p += gridDim.x) {
        const int np = npp[p];
        const float xc = ((float)coords[2 * p + 1] + 0.5f) * RES_ + XMIN_;
        const float yc = ((float)coords[2 * p + 0] + 0.5f) * RES_ + YMIN_;

        // Cooperative load of all 32 points (512B coalesced, 1 float/thread)
        ((float*)sh_pts)[t] = pillars[(size_t)p * 128 + t];
        __syncthreads();

        // z-mean over valid points (warp 0 butterfly)
        if (t < 32) {
            float z = (t < np) ? sh_pts[t].z : 0.f;
#pragma unroll
            for (int o = 16; o > 0; o >>= 1)
                z += __shfl_xor_sync(0xffffffffu, z, o);
            if (t == 0) sh_zm = z / fmaxf((float)np, 1.f);
        }
        __syncthreads();

        const float b1e = bb1 - xc * bxc - yc * byc - sh_zm * bzm;
        const int npairs = (np + 1) >> 1;

        // Layer 1 (+relu): halves split the pairs, one barrier
        for (int j = half; j < npairs; j += 2) {
            const int m0 = 2 * j;
            const int m1 = (2 * j + 1 < np) ? 2 * j + 1 : 2 * j;  // dup last if odd
            const float4 q0 = sh_pts[m0];
            const float4 q1 = sh_pts[m1];
            float h0 = fmaf(q0.w, a3, fmaf(q0.z, a2, fmaf(q0.y, a1, fmaf(q0.x, a0, b1e))));
            float h1 = fmaf(q1.w, a3, fmaf(q1.z, a2, fmaf(q1.y, a1, fmaf(q1.x, a0, b1e))));
            sh_h1[j][c64] = make_float2(fmaxf(h0, 0.f), fmaxf(h1, 0.f));
        }
        __syncthreads();

        // Layer 2 main loop: per pair, 8 broadcast LDS.128 feed 32 FFMA2
        // (2 channels x 16 k x 2 packed points), 4 independent chains.
        for (int j = 0; j < npairs; j++) {
            const ulonglong2* hb = (const ulonglong2*)sh_h1[j] + kg * 8;
            ull a0e = 0ull, a0o = 0ull, a1e = 0ull, a1o = 0ull;
#pragma unroll
            for (int i = 0; i < 8; i++) {
                ulonglong2 hv = hb[i];  // k = 16kg+2i, 16kg+2i+1 (both points)
                ffma2(a0e, hv.x, w2p[2 * i]);
                ffma2(a0o, hv.y, w2p[2 * i + 1]);
                ffma2(a1e, hv.x, w2p[16 + 2 * i]);
                ffma2(a1o, hv.y, w2p[16 + 2 * i + 1]);
            }
            fadd2(a0e, a0e, a0o);
            fadd2(a1e, a1e, a1o);
            sh_part[j][kg][c2]      = a0e;  // lanes consecutive -> conflict-free
            sh_part[j][kg][c2 + 32] = a1e;
        }
        __syncthreads();

        // Combine k-groups + running max; pair-parity split across halves.
        float runmax = NEG_;
        for (int j = half; j < npairs; j += 2) {
            ull p0 = sh_part[j][0][c64];
            ull p1 = sh_part[j][1][c64];
            ull p2 = sh_part[j][2][c64];
            ull p3 = sh_part[j][3][c64];
            fadd2(p0, p0, p1);
            fadd2(p2, p2, p3);
            fadd2(p0, p0, p2);
            float lo, hi;
            unpack2(p0, lo, hi);
            runmax = fmaxf(runmax, fmaxf(lo, hi));
        }
        sh_max[half][c64] = runmax;
        __syncthreads();

        // Final: merge parities, add bias after the max, relu after the max.
        if (t < 64) {
            float m = fmaxf(sh_max[0][c64], sh_max[1][c64]);
            out[(size_t)p * 64 + c64] = (np > 0) ? fmaxf(m + b2v, 0.f) : NEG_;
        }
    }
}

extern "C" void kernel_launch(void* const* d_in, const int* in_sizes, int n_in,
                              void* d_out, int out_size) {
    const float* pillars = (const float*)d_in[0];
    const int* coords    = (const int*)d_in[1];
    const int* npp       = (const int*)d_in[2];
    const float* W1    = (const float*)d_in[3];
    const float* b1    = (const float*)d_in[4];
    const float* g1    = (const float*)d_in[5];
    const float* beta1 = (const float*)d_in[6];
    const float* m1    = (const float*)d_in[7];
    const float* v1    = (const float*)d_in[8];
    const float* W2    = (const float*)d_in[9];
    const float* b2    = (const float*)d_in[10];
    const float* g2    = (const float*)d_in[11];
    const float* beta2 = (const float*)d_in[12];
    const float* m2    = (const float*)d_in[13];
    const float* v2    = (const float*)d_in[14];
    float* out = (float*)d_out;

    const int P = in_sizes[0] / (32 * 4);

    prep_kernel<<<1, 64>>>(W1, b1, g1, beta1, m1, v1, W2, b2, g2, beta2, m2, v2);
    pfn_kernel<<<592, 128>>>(pillars, coords, npp, out, P);
}